// round 2
// baseline (speedup 1.0000x reference)
#include <cuda_runtime.h>
#include <cstdint>

#define Bb 32
#define Ll 512
#define Dd 512
#define Ss 8

// Scratch (device globals: allocation-free per harness rules)
__device__ float g_A1[(size_t)Bb * Ss * Ll * Dd];  // [b][k][i][e]  256 MiB
__device__ float g_P1[Bb * Ll * Ss];
__device__ float g_P2[Bb * Ll * Ss];
__device__ float g_Q1[Bb * Ll * Ss];
__device__ float g_Q2[Bb * Ll * Ss];

__device__ __forceinline__ float sigf(float x) {
    return __fdividef(1.0f, 1.0f + __expf(-x));
}

// ---------------------------------------------------------------------------
// K1: projections. One warp per row (arg1 rows then arg2 rows).
// P = row @ Wg_half, Q = row @ V_half  (S=8 outputs each).
// ---------------------------------------------------------------------------
__global__ void proj_kernel(const float* __restrict__ arg1,
                            const float* __restrict__ arg2,
                            const float* __restrict__ Wg,
                            const float* __restrict__ V) {
    int w = (blockIdx.x * blockDim.x + threadIdx.x) >> 5;
    int lane = threadIdx.x & 31;

    const float* src;
    int row, woff;
    float *outP, *outQ;
    if (w < Bb * Ll) {
        src = arg1; row = w; woff = 0; outP = g_P1; outQ = g_Q1;
    } else {
        src = arg2; row = w - Bb * Ll; woff = Dd; outP = g_P2; outQ = g_Q2;
    }

    float aw[8] = {0.f,0.f,0.f,0.f,0.f,0.f,0.f,0.f};
    float av[8] = {0.f,0.f,0.f,0.f,0.f,0.f,0.f,0.f};

    for (int d = lane; d < Dd; d += 32) {
        float x = src[(size_t)row * Dd + d];
        const float4* wp = reinterpret_cast<const float4*>(Wg + (size_t)(woff + d) * Ss);
        const float4* vp = reinterpret_cast<const float4*>(V  + (size_t)(woff + d) * Ss);
        float4 w0 = wp[0], w1 = wp[1];
        float4 v0 = vp[0], v1 = vp[1];
        aw[0] += x * w0.x; aw[1] += x * w0.y; aw[2] += x * w0.z; aw[3] += x * w0.w;
        aw[4] += x * w1.x; aw[5] += x * w1.y; aw[6] += x * w1.z; aw[7] += x * w1.w;
        av[0] += x * v0.x; av[1] += x * v0.y; av[2] += x * v0.z; av[3] += x * v0.w;
        av[4] += x * v1.x; av[5] += x * v1.y; av[6] += x * v1.z; av[7] += x * v1.w;
    }

#pragma unroll
    for (int s = 0; s < 8; s++) {
#pragma unroll
        for (int o = 16; o > 0; o >>= 1) {
            aw[s] += __shfl_xor_sync(0xffffffffu, aw[s], o);
            av[s] += __shfl_xor_sync(0xffffffffu, av[s], o);
        }
    }
    if (lane == 0) {
#pragma unroll
        for (int s = 0; s < 8; s++) {
            outP[(size_t)row * Ss + s] = aw[s];
            outQ[(size_t)row * Ss + s] = av[s];
        }
    }
}

// ---------------------------------------------------------------------------
// K2: A1[b,k] = arg1[b] (L x D) @ Mr[k] (D x D).
// 128x128 tile, K-chunk 8, 256 threads, 8x8 micro-tile per thread.
// ---------------------------------------------------------------------------
__global__ __launch_bounds__(256) void mr_gemm_kernel(const float* __restrict__ arg1,
                                                      const float* __restrict__ Mr) {
    __shared__ float Asm[8][132];   // [d][i], padded: conflict-free transpose store
    __shared__ float Bsm[8][128];   // [d][e]

    int t = threadIdx.x;
    int bk = blockIdx.z;
    int bb = bk >> 3;
    int k  = bk & 7;
    int i0 = blockIdx.y * 128;
    int e0 = blockIdx.x * 128;

    const float* Abase = arg1 + ((size_t)bb * Ll + i0) * Dd;
    const float* Bbase = Mr + (size_t)k * Dd * Dd + e0;

    int tx = t & 15, ty = t >> 4;
    int li = t >> 1, lc = (t & 1) * 4;    // A load: row li, 4 cols at lc
    int ld = t >> 5, le = (t & 31) * 4;   // B load: row ld, 4 cols at le

    float acc[8][8];
#pragma unroll
    for (int i = 0; i < 8; i++)
#pragma unroll
        for (int j = 0; j < 8; j++) acc[i][j] = 0.f;

    for (int d0 = 0; d0 < Dd; d0 += 8) {
        float4 avv = *reinterpret_cast<const float4*>(Abase + (size_t)li * Dd + d0 + lc);
        float4 bvv = *reinterpret_cast<const float4*>(Bbase + (size_t)(d0 + ld) * Dd + le);
        __syncthreads();
        Asm[lc + 0][li] = avv.x;
        Asm[lc + 1][li] = avv.y;
        Asm[lc + 2][li] = avv.z;
        Asm[lc + 3][li] = avv.w;
        *reinterpret_cast<float4*>(&Bsm[ld][le]) = bvv;
        __syncthreads();

#pragma unroll
        for (int d = 0; d < 8; d++) {
            float a[8], bf[8];
            *reinterpret_cast<float4*>(&a[0])  = *reinterpret_cast<float4*>(&Asm[d][ty * 4]);
            *reinterpret_cast<float4*>(&a[4])  = *reinterpret_cast<float4*>(&Asm[d][ty * 4 + 64]);
            *reinterpret_cast<float4*>(&bf[0]) = *reinterpret_cast<float4*>(&Bsm[d][tx * 4]);
            *reinterpret_cast<float4*>(&bf[4]) = *reinterpret_cast<float4*>(&Bsm[d][tx * 4 + 64]);
#pragma unroll
            for (int ii = 0; ii < 8; ii++)
#pragma unroll
                for (int jj = 0; jj < 8; jj++) acc[ii][jj] += a[ii] * bf[jj];
        }
    }

    float* Cbase = g_A1 + ((size_t)(bb * 8 + k) * Ll + i0) * Dd + e0;
#pragma unroll
    for (int ii = 0; ii < 8; ii++) {
        int gi = ty * 4 + (ii & 3) + ((ii >> 2) * 64);
#pragma unroll
        for (int jh = 0; jh < 2; jh++) {
            float4 v = make_float4(acc[ii][jh * 4 + 0], acc[ii][jh * 4 + 1],
                                   acc[ii][jh * 4 + 2], acc[ii][jh * 4 + 3]);
            *reinterpret_cast<float4*>(Cbase + (size_t)gi * Dd + tx * 4 + jh * 64) = v;
        }
    }
}

// ---------------------------------------------------------------------------
// K3: fused bi-GEMM (8 simultaneous k-planes) + gated epilogue.
// Tile: 32 i x 64 j, 256 threads; thread micro-tile 2i x 4j x 8k = 64 accums.
// ---------------------------------------------------------------------------
__global__ __launch_bounds__(256) void fused_kernel(const float* __restrict__ arg2,
                                                    const float* __restrict__ Bg,
                                                    const float* __restrict__ bvec,
                                                    const float* __restrict__ U,
                                                    float* __restrict__ out) {
    __shared__ float As[8][32][34];  // [k][e][i], padded (even stride for float2)
    __shared__ float Bs[32][68];     // [e][j],   padded (float4-aligned stride)

    int t  = threadIdx.x;
    int bb = blockIdx.z;
    int it = blockIdx.y;
    int jt = blockIdx.x;
    int tx = t & 15, ty = t >> 4;

    float acc[8][2][4];
#pragma unroll
    for (int k = 0; k < 8; k++)
#pragma unroll
        for (int a = 0; a < 2; a++)
#pragma unroll
            for (int c = 0; c < 4; c++) acc[k][a][c] = 0.f;

    for (int e0 = 0; e0 < Dd; e0 += 32) {
        __syncthreads();
        // Load A1 chunk: 8k x 32i x 32e, transposed into [k][e][i]
#pragma unroll
        for (int m = 0; m < 8; m++) {
            int r  = t + 256 * m;
            int e4 = r & 7;
            int i  = (r >> 3) & 31;
            int k  = r >> 8;
            float4 v = *reinterpret_cast<const float4*>(
                g_A1 + ((size_t)(bb * 8 + k) * Ll + it * 32 + i) * Dd + e0 + e4 * 4);
            As[k][e4 * 4 + 0][i] = v.x;
            As[k][e4 * 4 + 1][i] = v.y;
            As[k][e4 * 4 + 2][i] = v.z;
            As[k][e4 * 4 + 3][i] = v.w;
        }
        // Load arg2 chunk: 64j x 32e, transposed into [e][j]
#pragma unroll
        for (int m = 0; m < 2; m++) {
            int r  = t + 256 * m;
            int e4 = r & 7;
            int j  = r >> 3;
            float4 v = *reinterpret_cast<const float4*>(
                arg2 + ((size_t)bb * Ll + jt * 64 + j) * Dd + e0 + e4 * 4);
            Bs[e4 * 4 + 0][j] = v.x;
            Bs[e4 * 4 + 1][j] = v.y;
            Bs[e4 * 4 + 2][j] = v.z;
            Bs[e4 * 4 + 3][j] = v.w;
        }
        __syncthreads();

#pragma unroll 8
        for (int e = 0; e < 32; e++) {
            float4 bj = *reinterpret_cast<const float4*>(&Bs[e][tx * 4]);
#pragma unroll
            for (int k = 0; k < 8; k++) {
                float2 ai = *reinterpret_cast<const float2*>(&As[k][e][ty * 2]);
                acc[k][0][0] += ai.x * bj.x;
                acc[k][0][1] += ai.x * bj.y;
                acc[k][0][2] += ai.x * bj.z;
                acc[k][0][3] += ai.x * bj.w;
                acc[k][1][0] += ai.y * bj.x;
                acc[k][1][1] += ai.y * bj.y;
                acc[k][1][2] += ai.y * bj.z;
                acc[k][1][3] += ai.y * bj.w;
            }
        }
    }

    // Epilogue
    float Bgv[8], Uv[8], bvv[8];
    *reinterpret_cast<float4*>(&Bgv[0]) = *reinterpret_cast<const float4*>(&Bg[0]);
    *reinterpret_cast<float4*>(&Bgv[4]) = *reinterpret_cast<const float4*>(&Bg[4]);
    *reinterpret_cast<float4*>(&Uv[0])  = *reinterpret_cast<const float4*>(&U[0]);
    *reinterpret_cast<float4*>(&Uv[4])  = *reinterpret_cast<const float4*>(&U[4]);
    *reinterpret_cast<float4*>(&bvv[0]) = *reinterpret_cast<const float4*>(&bvec[0]);
    *reinterpret_cast<float4*>(&bvv[4]) = *reinterpret_cast<const float4*>(&bvec[4]);
    float bU = 0.f;
#pragma unroll
    for (int k = 0; k < 8; k++) bU += bvv[k] * Uv[k];

    int gj0 = jt * 64 + tx * 4;
#pragma unroll
    for (int ii = 0; ii < 2; ii++) {
        int gi = it * 32 + ty * 2 + ii;
        float p1[8], q1[8];
        const float* p1p = g_P1 + ((size_t)bb * Ll + gi) * Ss;
        const float* q1p = g_Q1 + ((size_t)bb * Ll + gi) * Ss;
        *reinterpret_cast<float4*>(&p1[0]) = *reinterpret_cast<const float4*>(p1p);
        *reinterpret_cast<float4*>(&p1[4]) = *reinterpret_cast<const float4*>(p1p + 4);
        *reinterpret_cast<float4*>(&q1[0]) = *reinterpret_cast<const float4*>(q1p);
        *reinterpret_cast<float4*>(&q1[4]) = *reinterpret_cast<const float4*>(q1p + 4);

        float o[4];
#pragma unroll
        for (int jj = 0; jj < 4; jj++) {
            int gj = gj0 + jj;
            float p2[8], q2[8];
            const float* p2p = g_P2 + ((size_t)bb * Ll + gj) * Ss;
            const float* q2p = g_Q2 + ((size_t)bb * Ll + gj) * Ss;
            *reinterpret_cast<float4*>(&p2[0]) = *reinterpret_cast<const float4*>(p2p);
            *reinterpret_cast<float4*>(&p2[4]) = *reinterpret_cast<const float4*>(p2p + 4);
            *reinterpret_cast<float4*>(&q2[0]) = *reinterpret_cast<const float4*>(q2p);
            *reinterpret_cast<float4*>(&q2[4]) = *reinterpret_cast<const float4*>(q2p + 4);

            float sc = bU;
#pragma unroll
            for (int k = 0; k < 8; k++) {
                float g = sigf(p1[k] + p2[k] + Bgv[k]);
                float s = sigf(q1[k] + q2[k]);
                sc += Uv[k] * (acc[k][ii][jj] * g + s * (1.0f - g));
            }
            o[jj] = sigf(sc);
        }
        *reinterpret_cast<float4*>(out + ((size_t)bb * Ll + gi) * Ll + gj0) =
            make_float4(o[0], o[1], o[2], o[3]);
    }
}

// ---------------------------------------------------------------------------
extern "C" void kernel_launch(void* const* d_in, const int* in_sizes, int n_in,
                              void* d_out, int out_size) {
    const float* arg1 = (const float*)d_in[0];
    const float* arg2 = (const float*)d_in[1];
    const float* Wg   = (const float*)d_in[2];
    const float* Bg   = (const float*)d_in[3];
    const float* Mr   = (const float*)d_in[4];
    const float* V    = (const float*)d_in[5];
    const float* bvec = (const float*)d_in[6];
    const float* U    = (const float*)d_in[7];
    float* out = (float*)d_out;

    // K1: 2*B*L rows, one warp each, 8 warps/block
    proj_kernel<<<(2 * Bb * Ll) / 8, 256>>>(arg1, arg2, Wg, V);

    // K2: per (b,k): 512x512x512 GEMM in 128x128 tiles
    dim3 g2(Dd / 128, Ll / 128, Bb * Ss);
    mr_gemm_kernel<<<g2, 256>>>(arg1, Mr);

    // K3: fused bi-GEMM + epilogue, 32x64 (i,j) tiles
    dim3 g3(Ll / 64, Ll / 32, Bb);
    fused_kernel<<<g3, 256>>>(arg2, Bg, bvec, U, out);
}

// round 4
// speedup vs baseline: 1.8317x; 1.8317x over previous
#include <cuda_runtime.h>
#include <cuda_bf16.h>
#include <cstdint>

#define Bb 32
#define Ll 512
#define Dd 512
#define Ss 8

// ---------------------------------------------------------------------------
// Device-global scratch (no allocations allowed)
// ---------------------------------------------------------------------------
__device__ __nv_bfloat16 g_A2hi[(size_t)Bb * Ss * Ll * Dd];  // 128 MiB
__device__ __nv_bfloat16 g_A2lo[(size_t)Bb * Ss * Ll * Dd];  // 128 MiB
__device__ float g_P1[Bb * Ll * Ss];   // [b][i][k]
__device__ float g_Q1[Bb * Ll * Ss];
__device__ float g_P2t[Bb * Ss * Ll];  // [b][k][j]
__device__ float g_Q2t[Bb * Ss * Ll];

// ---------------------------------------------------------------------------
// Helpers
// ---------------------------------------------------------------------------
__device__ __forceinline__ uint32_t smem_u32(const void* p) {
    uint32_t a;
    asm("{ .reg .u64 t; cvta.to.shared.u64 t, %1; cvt.u32.u64 %0, t; }"
        : "=r"(a) : "l"(p));
    return a;
}

__device__ __forceinline__ void ldsm4(uint32_t* r, uint32_t a) {
    asm volatile("ldmatrix.sync.aligned.m8n8.x4.shared.b16 {%0,%1,%2,%3}, [%4];"
                 : "=r"(r[0]), "=r"(r[1]), "=r"(r[2]), "=r"(r[3]) : "r"(a) : "memory");
}
__device__ __forceinline__ void ldsm2(uint32_t* r, uint32_t a) {
    asm volatile("ldmatrix.sync.aligned.m8n8.x2.shared.b16 {%0,%1}, [%2];"
                 : "=r"(r[0]), "=r"(r[1]) : "r"(a) : "memory");
}
__device__ __forceinline__ void mma_bf16(float* c, const uint32_t* a, const uint32_t* b) {
    asm volatile("mma.sync.aligned.m16n8k16.row.col.f32.bf16.bf16.f32 "
                 "{%0,%1,%2,%3}, {%4,%5,%6,%7}, {%8,%9}, {%0,%1,%2,%3};"
                 : "+f"(c[0]), "+f"(c[1]), "+f"(c[2]), "+f"(c[3])
                 : "r"(a[0]), "r"(a[1]), "r"(a[2]), "r"(a[3]), "r"(b[0]), "r"(b[1]));
}

#define CP16(dst, src) \
    asm volatile("cp.async.ca.shared.global [%0], [%1], 16;" :: "r"(dst), "l"(src) : "memory")
#define CPCOMMIT() asm volatile("cp.async.commit_group;" ::: "memory")
#define CPWAIT1() asm volatile("cp.async.wait_group 1;" ::: "memory")
#define CPWAIT0() asm volatile("cp.async.wait_group 0;" ::: "memory")

__device__ __forceinline__ uint32_t pack_bf16x2(float a, float b) {
    uint32_t h;
    asm("cvt.rn.bf16x2.f32 %0, %1, %2;" : "=r"(h) : "f"(b), "f"(a));  // low=a
    return h;
}
// split (a,b) fp32 pair -> bf16x2 hi + bf16x2 lo residual
__device__ __forceinline__ void split2(float a, float b, uint32_t& h, uint32_t& l) {
    h = pack_bf16x2(a, b);
    float ha = __uint_as_float(h << 16), hb = __uint_as_float(h & 0xFFFF0000u);
    l = pack_bf16x2(a - ha, b - hb);
}
// split float4 -> two uint2 stores (hi / lo), 8B each
__device__ __forceinline__ void split_sts(char* hi_b, char* lo_b, uint32_t off, float4 v) {
    uint32_t h0, l0, h1, l1;
    split2(v.x, v.y, h0, l0);
    split2(v.z, v.w, h1, l1);
    *reinterpret_cast<uint2*>(hi_b + off) = make_uint2(h0, h1);
    *reinterpret_cast<uint2*>(lo_b + off) = make_uint2(l0, l1);
}

// FMA-pipe-only sigmoid. abs err ~1.5e-5, zero MUFU.
__device__ __forceinline__ float sig_fma(float x) {
    float ax = fminf(fabsf(x), 20.0f);
    float y = -1.44269504f * ax;
    float t = y + 12582912.0f;
    int n = __float_as_int(t) - 0x4B400000;
    float f = y - (t - 12582912.0f);
    float p = 1.33335581e-3f;
    p = fmaf(p, f, 9.61812910e-3f);
    p = fmaf(p, f, 5.55041086e-2f);
    p = fmaf(p, f, 2.40226507e-1f);
    p = fmaf(p, f, 6.93147181e-1f);
    p = fmaf(p, f, 1.0f);
    float E = __int_as_float(__float_as_int(p) + (n << 23));  // e^{-ax}
    float w = 1.0f + E;
    float r = __int_as_float(0x7EF127EAu - __float_as_int(w));
    r = r * (2.0f - w * r);
    r = r * (2.0f - w * r);
    return x >= 0.0f ? r : 1.0f - r;
}

// ---------------------------------------------------------------------------
// K1: projections (one warp per row). P2/Q2 stored transposed [b][k][j].
// ---------------------------------------------------------------------------
__global__ void proj_kernel(const float* __restrict__ arg1,
                            const float* __restrict__ arg2,
                            const float* __restrict__ Wg,
                            const float* __restrict__ V) {
    int w = (blockIdx.x * blockDim.x + threadIdx.x) >> 5;
    int lane = threadIdx.x & 31;
    bool first = (w < Bb * Ll);
    const float* src = first ? arg1 : arg2;
    int row = first ? w : w - Bb * Ll;
    int woff = first ? 0 : Dd;

    float aw[8] = {0,0,0,0,0,0,0,0}, av[8] = {0,0,0,0,0,0,0,0};
    for (int d = lane; d < Dd; d += 32) {
        float x = src[(size_t)row * Dd + d];
        const float4* wp = reinterpret_cast<const float4*>(Wg + (size_t)(woff + d) * Ss);
        const float4* vp = reinterpret_cast<const float4*>(V  + (size_t)(woff + d) * Ss);
        float4 w0 = wp[0], w1 = wp[1], v0 = vp[0], v1 = vp[1];
        aw[0] += x*w0.x; aw[1] += x*w0.y; aw[2] += x*w0.z; aw[3] += x*w0.w;
        aw[4] += x*w1.x; aw[5] += x*w1.y; aw[6] += x*w1.z; aw[7] += x*w1.w;
        av[0] += x*v0.x; av[1] += x*v0.y; av[2] += x*v0.z; av[3] += x*v0.w;
        av[4] += x*v1.x; av[5] += x*v1.y; av[6] += x*v1.z; av[7] += x*v1.w;
    }
#pragma unroll
    for (int s = 0; s < 8; s++)
#pragma unroll
        for (int o = 16; o > 0; o >>= 1) {
            aw[s] += __shfl_xor_sync(0xffffffffu, aw[s], o);
            av[s] += __shfl_xor_sync(0xffffffffu, av[s], o);
        }
    if (lane == 0) {
        if (first) {
#pragma unroll
            for (int s = 0; s < 8; s++) {
                g_P1[(size_t)row * Ss + s] = aw[s];
                g_Q1[(size_t)row * Ss + s] = av[s];
            }
        } else {
            int bbv = row >> 9, j = row & 511;
#pragma unroll
            for (int s = 0; s < 8; s++) {
                g_P2t[((size_t)bbv * Ss + s) * Ll + j] = aw[s];
                g_Q2t[((size_t)bbv * Ss + s) * Ll + j] = av[s];
            }
        }
    }
}

// ---------------------------------------------------------------------------
// K2: A2[b,k][j,d] = arg2[b] @ Mr[k]^T via mma.sync bf16, 3-pass hi/lo.
// CTA 128x128, KC=32, 3 SMEM buffers, warp tile 64m x 32n.
// Buffer layout: Ahi | Alo | Bhi | Blo, rows padded to 80B (conflict-free LDSM).
// ---------------------------------------------------------------------------
#define S1_OP   (128 * 80)       // 10240 bytes per operand variant
#define S1_BUF  (4 * S1_OP)      // 40960 per buffer
#define S1_SMEM (3 * S1_BUF)     // 122880

__global__ __launch_bounds__(256, 1) void gemm1_kernel(const float* __restrict__ arg2,
                                                       const float* __restrict__ Mr) {
    extern __shared__ char smem[];
    uint32_t sb = smem_u32(smem);
    int t = threadIdx.x, lane = t & 31, wid = t >> 5;
    int bz = blockIdx.z, bbv = bz >> 3, kk = bz & 7;
    int j0 = blockIdx.y * 128, d0 = blockIdx.x * 128;
    int wm = wid & 1, wn = wid >> 1;  // 2x4 warps, warp tile 64m x 32n

    uint32_t aoff[4], boff[4];
#pragma unroll
    for (int mt = 0; mt < 4; mt++)
        aoff[mt] = (uint32_t)((wm * 64 + mt * 16 + (lane & 15)) * 80 + (lane >> 4) * 16);
#pragma unroll
    for (int nt = 0; nt < 4; nt++)
        boff[nt] = (uint32_t)((wn * 32 + nt * 8 + (lane & 7)) * 80 + ((lane >> 3) & 1) * 16);

    int lr = t >> 1, lcb = (t & 1) * 16;
    const float* aAg = arg2 + ((size_t)bbv * Ll + j0 + lr) * Dd + lcb;
    const float* aBg = Mr + ((size_t)kk * Dd + d0 + lr) * Dd + lcb;
    uint32_t stoff = (uint32_t)(lr * 80 + lcb * 2);

    float acc[4][4][4];
#pragma unroll
    for (int mt = 0; mt < 4; mt++)
#pragma unroll
        for (int nt = 0; nt < 4; nt++)
#pragma unroll
            for (int q = 0; q < 4; q++) acc[mt][nt][q] = 0.f;

    float4 ra[4], rb[4];
#pragma unroll
    for (int q = 0; q < 4; q++) {
        ra[q] = *reinterpret_cast<const float4*>(aAg + q * 4);
        rb[q] = *reinterpret_cast<const float4*>(aBg + q * 4);
    }
    {
        char* buf = smem;
#pragma unroll
        for (int q = 0; q < 4; q++) {
            split_sts(buf, buf + S1_OP, stoff + q * 8, ra[q]);
            split_sts(buf + 2 * S1_OP, buf + 3 * S1_OP, stoff + q * 8, rb[q]);
        }
    }
    __syncthreads();

#pragma unroll 1
    for (int c = 0; c < 16; c++) {
        if (c < 15) {
            const float* pA = aAg + (c + 1) * 32;
            const float* pB = aBg + (c + 1) * 32;
#pragma unroll
            for (int q = 0; q < 4; q++) {
                ra[q] = *reinterpret_cast<const float4*>(pA + q * 4);
                rb[q] = *reinterpret_cast<const float4*>(pB + q * 4);
            }
        }
        uint32_t bufb = sb + (c % 3) * S1_BUF;
#pragma unroll
        for (int k16 = 0; k16 < 2; k16++) {
            uint32_t ahi[4][4], alo[4][4], bhi[4][2], blo[4][2];
#pragma unroll
            for (int mt = 0; mt < 4; mt++) {
                ldsm4(ahi[mt], bufb + aoff[mt] + k16 * 32);
                ldsm4(alo[mt], bufb + S1_OP + aoff[mt] + k16 * 32);
            }
#pragma unroll
            for (int nt = 0; nt < 4; nt++) {
                ldsm2(bhi[nt], bufb + 2 * S1_OP + boff[nt] + k16 * 32);
                ldsm2(blo[nt], bufb + 3 * S1_OP + boff[nt] + k16 * 32);
            }
#pragma unroll
            for (int mt = 0; mt < 4; mt++)
#pragma unroll
                for (int nt = 0; nt < 4; nt++) {
                    mma_bf16(acc[mt][nt], ahi[mt], bhi[nt]);
                    mma_bf16(acc[mt][nt], ahi[mt], blo[nt]);
                    mma_bf16(acc[mt][nt], alo[mt], bhi[nt]);
                }
        }
        if (c < 15) {
            char* buf = smem + ((c + 1) % 3) * S1_BUF;
#pragma unroll
            for (int q = 0; q < 4; q++) {
                split_sts(buf, buf + S1_OP, stoff + q * 8, ra[q]);
                split_sts(buf + 2 * S1_OP, buf + 3 * S1_OP, stoff + q * 8, rb[q]);
            }
        }
        __syncthreads();
    }

    // Drain: split fp32 acc -> bf16 hi/lo to gmem
    size_t plane = (size_t)bz * Ll * Dd;
#pragma unroll
    for (int mt = 0; mt < 4; mt++) {
        int jr = j0 + wm * 64 + mt * 16 + (lane >> 2);
#pragma unroll
        for (int nt = 0; nt < 4; nt++) {
            int dc = d0 + wn * 32 + nt * 8 + (lane & 3) * 2;
            size_t x0 = plane + (size_t)jr * Dd + dc;
            size_t x1 = x0 + (size_t)8 * Dd;
            uint32_t h, l;
            split2(acc[mt][nt][0], acc[mt][nt][1], h, l);
            *reinterpret_cast<uint32_t*>(&g_A2hi[x0]) = h;
            *reinterpret_cast<uint32_t*>(&g_A2lo[x0]) = l;
            split2(acc[mt][nt][2], acc[mt][nt][3], h, l);
            *reinterpret_cast<uint32_t*>(&g_A2hi[x1]) = h;
            *reinterpret_cast<uint32_t*>(&g_A2lo[x1]) = l;
        }
    }
}

// ---------------------------------------------------------------------------
// K3: bi = arg1 @ A2^T for 8 planes + fused gated epilogue.
// CTA 64i x 64j; arg1 tile (split) resident in SMEM; A2 streamed via cp.async.
// ---------------------------------------------------------------------------
#define S2_AOP  (64 * 1040)               // 66560 per variant
#define S2_BOP  (64 * 80)                 // 5120 per variant
#define S2_BBUF (2 * S2_BOP)              // 10240 (hi|lo)
#define S2_BOFF (2 * S2_AOP)              // 133120
#define S2_SMEM (S2_BOFF + 3 * S2_BBUF)   // 163840

__device__ __forceinline__ void s2_issue(int m, int t, int bbv, int j0, uint32_t sb) {
    int k = m >> 4, c = m & 15;
    uint32_t dstb = sb + S2_BOFF + (m % 3) * S2_BBUF;
    size_t srow = ((size_t)(bbv * 8 + k) * Ll + j0);
#pragma unroll
    for (int v = 0; v < 2; v++) {
        int idx = t + v * 256;
        int var = idx >> 8, rr = (idx & 255) >> 2, seg = idx & 3;
        const __nv_bfloat16* s =
            (var ? g_A2lo : g_A2hi) + (srow + rr) * Dd + c * 32 + seg * 8;
        CP16(dstb + var * S2_BOP + rr * 80 + seg * 16, s);
    }
    CPCOMMIT();
}

__global__ __launch_bounds__(256, 1) void gemm2_kernel(const float* __restrict__ arg1,
                                                       const float* __restrict__ Bg,
                                                       const float* __restrict__ bvec,
                                                       const float* __restrict__ U,
                                                       float* __restrict__ out) {
    extern __shared__ char smem[];
    uint32_t sb = smem_u32(smem);
    int t = threadIdx.x, lane = t & 31, wid = t >> 5;
    int bbv = blockIdx.z, i0 = blockIdx.y * 64, j0 = blockIdx.x * 64;
    int wi = wid & 3, wj = wid >> 2;  // 4x2 warps, warp tile 16i x 32j

    // Load arg1 tile resident (split hi/lo)
    {
        int r = t >> 2;
        const float* src = arg1 + ((size_t)bbv * Ll + i0 + r) * Dd;
        char* hb = smem;
        char* lb = smem + S2_AOP;
#pragma unroll
        for (int q = 0; q < 32; q++) {
            int col = (t & 3) * 4 + q * 16;
            float4 v = *reinterpret_cast<const float4*>(src + col);
            split_sts(hb + r * 1040 + col * 2, lb + r * 1040 + col * 2, 0, v);
        }
    }
    s2_issue(0, t, bbv, j0, sb);
    __syncthreads();

    uint32_t aoffA = (uint32_t)((wi * 16 + (lane & 15)) * 1040 + (lane >> 4) * 16);
    uint32_t boffB[4];
#pragma unroll
    for (int nt = 0; nt < 4; nt++)
        boffB[nt] = (uint32_t)((wj * 32 + nt * 8 + (lane & 7)) * 80 + ((lane >> 3) & 1) * 16);

    float bU = 0.f;
#pragma unroll
    for (int s = 0; s < 8; s++) bU += bvec[s] * U[s];
    float sc[4][2][2];
#pragma unroll
    for (int nt = 0; nt < 4; nt++)
#pragma unroll
        for (int p = 0; p < 2; p++) { sc[nt][p][0] = bU; sc[nt][p][1] = bU; }

    int iL = i0 + wi * 16 + (lane >> 2);
    int iH = iL + 8;

#pragma unroll 1
    for (int k = 0; k < 8; k++) {
        float acc[4][4];
#pragma unroll
        for (int nt = 0; nt < 4; nt++)
#pragma unroll
            for (int q = 0; q < 4; q++) acc[nt][q] = 0.f;

#pragma unroll 1
        for (int c = 0; c < 16; c++) {
            int m = k * 16 + c;
            if (m < 127) { s2_issue(m + 1, t, bbv, j0, sb); CPWAIT1(); }
            else CPWAIT0();
            __syncthreads();
            uint32_t bufb = sb + S2_BOFF + (m % 3) * S2_BBUF;
#pragma unroll
            for (int k16 = 0; k16 < 2; k16++) {
                uint32_t ahi[4], alo[4], bhi[4][2], blo[4][2];
                ldsm4(ahi, sb + aoffA + c * 64 + k16 * 32);
                ldsm4(alo, sb + S2_AOP + aoffA + c * 64 + k16 * 32);
#pragma unroll
                for (int nt = 0; nt < 4; nt++) {
                    ldsm2(bhi[nt], bufb + boffB[nt] + k16 * 32);
                    ldsm2(blo[nt], bufb + S2_BOP + boffB[nt] + k16 * 32);
                }
#pragma unroll
                for (int nt = 0; nt < 4; nt++) {
                    mma_bf16(acc[nt], ahi, bhi[nt]);
                    mma_bf16(acc[nt], ahi, blo[nt]);
                    mma_bf16(acc[nt], alo, bhi[nt]);
                }
            }
        }
        // Fused epilogue for plane k
        float BgK = Bg[k], Uk = U[k];
        float p1L = g_P1[((size_t)bbv * Ll + iL) * Ss + k] + BgK;
        float p1H = g_P1[((size_t)bbv * Ll + iH) * Ss + k] + BgK;
        float q1L = g_Q1[((size_t)bbv * Ll + iL) * Ss + k];
        float q1H = g_Q1[((size_t)bbv * Ll + iH) * Ss + k];
        const float* p2b = g_P2t + ((size_t)(bbv * 8 + k)) * Ll + j0 + wj * 32;
        const float* q2b = g_Q2t + ((size_t)(bbv * 8 + k)) * Ll + j0 + wj * 32;
#pragma unroll
        for (int nt = 0; nt < 4; nt++)
#pragma unroll
            for (int e = 0; e < 2; e++) {
                int jc = nt * 8 + (lane & 3) * 2 + e;
                float p2 = p2b[jc], q2 = q2b[jc];
                float gL = sig_fma(p1L + p2), sL = sig_fma(q1L + q2);
                float gH = sig_fma(p1H + p2), sH = sig_fma(q1H + q2);
                sc[nt][0][e] += Uk * fmaf(acc[nt][e] - sL, gL, sL);
                sc[nt][1][e] += Uk * fmaf(acc[nt][2 + e] - sH, gH, sH);
            }
    }

    // Final sigmoid + store
#pragma unroll
    for (int nt = 0; nt < 4; nt++) {
        int jc = j0 + wj * 32 + nt * 8 + (lane & 3) * 2;
        float2 v0 = make_float2(sig_fma(sc[nt][0][0]), sig_fma(sc[nt][0][1]));
        float2 v1 = make_float2(sig_fma(sc[nt][1][0]), sig_fma(sc[nt][1][1]));
        *reinterpret_cast<float2*>(&out[((size_t)bbv * Ll + iL) * Ll + jc]) = v0;
        *reinterpret_cast<float2*>(&out[((size_t)bbv * Ll + iH) * Ll + jc]) = v1;
    }
}

// ---------------------------------------------------------------------------
extern "C" void kernel_launch(void* const* d_in, const int* in_sizes, int n_in,
                              void* d_out, int out_size) {
    const float* arg1 = (const float*)d_in[0];
    const float* arg2 = (const float*)d_in[1];
    const float* Wg   = (const float*)d_in[2];
    const float* Bg   = (const float*)d_in[3];
    const float* Mr   = (const float*)d_in[4];
    const float* V    = (const float*)d_in[5];
    const float* bvec = (const float*)d_in[6];
    const float* U    = (const float*)d_in[7];
    float* out = (float*)d_out;

    cudaFuncSetAttribute(gemm1_kernel, cudaFuncAttributeMaxDynamicSharedMemorySize, S1_SMEM);
    cudaFuncSetAttribute(gemm2_kernel, cudaFuncAttributeMaxDynamicSharedMemorySize, S2_SMEM);

    proj_kernel<<<(2 * Bb * Ll) / 8, 256>>>(arg1, arg2, Wg, V);

    dim3 g1(Dd / 128, Ll / 128, Bb * Ss);
    gemm1_kernel<<<g1, 256, S1_SMEM>>>(arg2, Mr);

    dim3 g2(Ll / 64, Ll / 64, Bb);
    gemm2_kernel<<<g2, 256, S2_SMEM>>>(arg1, Bg, bvec, U, out);
}